// round 13
// baseline (speedup 1.0000x reference)
#include <cuda_runtime.h>
#include <cuda_bf16.h>
#include <cuda_fp16.h>
#include <cstdint>

#define N_NODE 100000
#define N_TOT  102000
#define NFEAT  256
#define NDIM   128
#define CAP    64
#define SPILL_MAX 8192

typedef unsigned long long u64;

// ===========================================================================
// Device scratch
// ===========================================================================
__device__ int  g_cnt[2][N_TOT];
__device__ u64  g_rec[2][(size_t)N_TOT * CAP];   // low32: col*NDIM, high32: val
__device__ int  g_spill_cnt;
__device__ int4 g_spill[SPILL_MAX];
__device__ __align__(16) uint4 g_Whi_pk[4096];   // 64 KB prepacked W hi
__device__ __align__(16) uint4 g_Wlo_pk[4096];   // 64 KB prepacked W lo
__device__ __align__(16) __half g_x1h[(size_t)N_TOT * NDIM];  // 26 MB fp16 x1

// ---------------------------------------------------------------------------
__device__ __forceinline__ void split_pack(const float4* v, uint32_t* hp, uint32_t* lp) {
    const float* f = (const float*)v;
#pragma unroll
    for (int i = 0; i < 8; i++) {
        __nv_bfloat16 h0 = __float2bfloat16(f[2*i]);
        __nv_bfloat16 h1 = __float2bfloat16(f[2*i+1]);
        __nv_bfloat16 l0 = __float2bfloat16(f[2*i]   - __bfloat162float(h0));
        __nv_bfloat16 l1 = __float2bfloat16(f[2*i+1] - __bfloat162float(h1));
        hp[i] = (uint32_t)__bfloat16_as_ushort(h0) | ((uint32_t)__bfloat16_as_ushort(h1) << 16);
        lp[i] = (uint32_t)__bfloat16_as_ushort(l0) | ((uint32_t)__bfloat16_as_ushort(l1) << 16);
    }
}
__device__ __forceinline__ void split_pack8(const float4* v, uint32_t* hp, uint32_t* lp) {
    const float* f = (const float*)v;
#pragma unroll
    for (int i = 0; i < 4; i++) {
        __nv_bfloat16 h0 = __float2bfloat16(f[2*i]);
        __nv_bfloat16 h1 = __float2bfloat16(f[2*i+1]);
        __nv_bfloat16 l0 = __float2bfloat16(f[2*i]   - __bfloat162float(h0));
        __nv_bfloat16 l1 = __float2bfloat16(f[2*i+1] - __bfloat162float(h1));
        hp[i] = (uint32_t)__bfloat16_as_ushort(h0) | ((uint32_t)__bfloat16_as_ushort(h1) << 16);
        lp[i] = (uint32_t)__bfloat16_as_ushort(l0) | ((uint32_t)__bfloat16_as_ushort(l1) << 16);
    }
}

// ---------------------------------------------------------------------------
// zero counters + (block 0) prepack W
// ---------------------------------------------------------------------------
__global__ void zero_cnt_kernel(const float* __restrict__ W) {
    int i = blockIdx.x * blockDim.x + threadIdx.x;
    int n = 2 * N_TOT;
    int stride = gridDim.x * blockDim.x;
    for (int j = i; j < n; j += stride)
        ((int*)g_cnt)[j] = 0;
    if (i == 0) g_spill_cnt = 0;

    if (blockIdx.x == 0) {
        const int t = threadIdx.x;
        const int r = t >> 1;
        const int half = t & 1;
        const float* wrow = W + (size_t)r * NFEAT;
        char* hB = (char*)g_Whi_pk;
        char* lB = (char*)g_Wlo_pk;
        for (int ki = 0; ki < 8; ki++) {
            float4 v[4];
#pragma unroll
            for (int q = 0; q < 4; q++)
                v[q] = __ldg((const float4*)(wrow + ki * 32 + half * 16) + q);
            uint32_t hp[8], lp[8];
            split_pack(v, hp, lp);
            int sw = r & 3;
#pragma unroll
            for (int cc = 0; cc < 2; cc++) {
                int ch = (half * 2 + cc) ^ sw;
                int off = ki * 8192 + r * 64 + ch * 16;
                *(uint4*)(hB + off) = make_uint4(hp[cc*4], hp[cc*4+1], hp[cc*4+2], hp[cc*4+3]);
                *(uint4*)(lB + off) = make_uint4(lp[cc*4], lp[cc*4+1], lp[cc*4+2], lp[cc*4+3]);
            }
        }
    }
}

// ---------------------------------------------------------------------------
// ELL placement: records carry pre-scaled column (col*NDIM)
// ---------------------------------------------------------------------------
__global__ __launch_bounds__(256) void place_kernel(
    const int* __restrict__ erow1, const int* __restrict__ ecol1, const float* __restrict__ eval1,
    const int* __restrict__ erow2, const int* __restrict__ ecol2, const float* __restrict__ eval2,
    int E, int perAdj)
{
    int idx = blockIdx.x * blockDim.x + threadIdx.x;
    int a = 0;
    if (idx >= perAdj) { a = 1; idx -= perAdj; if (idx >= perAdj) return; }
    const int*   erow = a ? erow2 : erow1;
    const int*   ecol = a ? ecol2 : ecol1;
    const float* eval = a ? eval2 : eval1;
    u64* rec = g_rec[a];
    int* cnt = g_cnt[a];

    int e0 = idx * 8;
    int nn = (e0 + 8 <= E) ? 8 : (E - e0);
    if (nn <= 0) return;

    int rr[8], cc[8]; float vv[8];
#pragma unroll
    for (int q = 0; q < 2; q++) {
        if (e0 + q * 4 + 4 <= E) {
            int4   r4 = *(const int4*)(erow + e0 + q * 4);
            int4   c4 = *(const int4*)(ecol + e0 + q * 4);
            float4 v4 = *(const float4*)(eval + e0 + q * 4);
            rr[q*4+0] = r4.x; rr[q*4+1] = r4.y; rr[q*4+2] = r4.z; rr[q*4+3] = r4.w;
            cc[q*4+0] = c4.x; cc[q*4+1] = c4.y; cc[q*4+2] = c4.z; cc[q*4+3] = c4.w;
            vv[q*4+0] = v4.x; vv[q*4+1] = v4.y; vv[q*4+2] = v4.z; vv[q*4+3] = v4.w;
        } else {
            for (int i = q * 4; i < nn; i++) {
                rr[i] = __ldg(erow + e0 + i);
                cc[i] = __ldg(ecol + e0 + i);
                vv[i] = __ldg(eval + e0 + i);
            }
        }
    }

    int pos[8];
#pragma unroll
    for (int i = 0; i < 8; i++)
        if (i < nn) pos[i] = atomicAdd(&cnt[rr[i]], 1);

#pragma unroll
    for (int i = 0; i < 8; i++) {
        if (i < nn) {
            u64 r8 = (u64)(unsigned)(cc[i] * NDIM)
                   | ((u64)__float_as_uint(vv[i]) << 32);
            if (pos[i] < CAP) {
                rec[(size_t)rr[i] * CAP + pos[i]] = r8;
            } else {
                int s = atomicAdd(&g_spill_cnt, 1);
                if (s < SPILL_MAX)
                    g_spill[s] = make_int4(rr[i] | (a << 30), cc[i],
                                           (int)__float_as_uint(vv[i]), 0);
            }
        }
    }
}

// ---------------------------------------------------------------------------
// SpMM v4b: fp16 gathers (uint2/lane), MLP=8, pre-scaled column index.
// ---------------------------------------------------------------------------
__global__ __launch_bounds__(256) void spmm_kernel(
    float* __restrict__ x2, float* __restrict__ x3)
{
    const int lane  = threadIdx.x & 31;
    const int warp0 = (int)(((size_t)blockIdx.x * blockDim.x + threadIdx.x) >> 5);
    const int nw    = (gridDim.x * blockDim.x) >> 5;
    const __half* xh = g_x1h;

    for (int gw = warp0; gw < 2 * N_TOT; gw += nw) {
        const int a = (gw >= N_TOT) ? 1 : 0;
        const int r = a ? (gw - N_TOT) : gw;

        int m = g_cnt[a][r];
        if (m > CAP) m = CAP;
        const u64* rp = g_rec[a] + (size_t)r * CAP;

        u64 myrec = 0;
        if (lane < m) myrec = __ldg(rp + lane);

        float4 accA = make_float4(0.f, 0.f, 0.f, 0.f);
        float4 accB = make_float4(0.f, 0.f, 0.f, 0.f);
        const int m1 = (m < 32) ? m : 32;
        int k = 0;

        for (; k + 8 <= m1; k += 8) {
            uint2 u[8]; float v[8];
#pragma unroll
            for (int i = 0; i < 8; i++) {
                u64 q = __shfl_sync(0xffffffffu, myrec, k + i);
                v[i] = __uint_as_float((unsigned)(q >> 32));
                u[i] = __ldg((const uint2*)(xh + (unsigned)q) + lane);
            }
#pragma unroll
            for (int i = 0; i < 8; i++) {
                float2 f01 = __half22float2(*(const __half2*)&u[i].x);
                float2 f23 = __half22float2(*(const __half2*)&u[i].y);
                float4* A = (i & 1) ? &accB : &accA;
                A->x = fmaf(v[i], f01.x, A->x);
                A->y = fmaf(v[i], f01.y, A->y);
                A->z = fmaf(v[i], f23.x, A->z);
                A->w = fmaf(v[i], f23.y, A->w);
            }
        }
        for (; k < m1; k++) {
            u64 q = __shfl_sync(0xffffffffu, myrec, k);
            float v = __uint_as_float((unsigned)(q >> 32));
            uint2 u = __ldg((const uint2*)(xh + (unsigned)q) + lane);
            float2 f01 = __half22float2(*(const __half2*)&u.x);
            float2 f23 = __half22float2(*(const __half2*)&u.y);
            accA.x = fmaf(v, f01.x, accA.x);
            accA.y = fmaf(v, f01.y, accA.y);
            accA.z = fmaf(v, f23.x, accA.z);
            accA.w = fmaf(v, f23.y, accA.w);
        }
        for (; k < m; k++) {           // rare: degree > 32
            u64 q = __ldg(rp + k);
            float v = __uint_as_float((unsigned)(q >> 32));
            uint2 u = __ldg((const uint2*)(xh + (unsigned)q) + lane);
            float2 f01 = __half22float2(*(const __half2*)&u.x);
            float2 f23 = __half22float2(*(const __half2*)&u.y);
            accA.x = fmaf(v, f01.x, accA.x);
            accA.y = fmaf(v, f01.y, accA.y);
            accA.z = fmaf(v, f23.x, accA.z);
            accA.w = fmaf(v, f23.y, accA.w);
        }

        float4 acc;
        acc.x = accA.x + accB.x; acc.y = accA.y + accB.y;
        acc.z = accA.z + accB.z; acc.w = accA.w + accB.w;
        float* outp = (a ? x3 : x2) + (size_t)r * NDIM;
        ((float4*)outp)[lane] = acc;
    }
}

__global__ __launch_bounds__(256) void spill_kernel(
    const float* __restrict__ x1, float* __restrict__ x2, float* __restrict__ x3)
{
    int nspill = g_spill_cnt;
    if (nspill > SPILL_MAX) nspill = SPILL_MAX;
    int lane = threadIdx.x & 31;
    int warp = (blockIdx.x * blockDim.x + threadIdx.x) >> 5;
    int nwarps = (gridDim.x * blockDim.x) >> 5;
    for (int s = warp; s < nspill; s += nwarps) {
        int4 e = g_spill[s];
        int a = (e.x >> 30) & 1;
        int r = e.x & 0x3fffffff;
        float v = __uint_as_float((unsigned)e.z);
        float4 p = __ldg((const float4*)(x1 + (size_t)e.y * NDIM) + lane);
        float* dst = (a ? x3 : x2) + (size_t)r * NDIM + lane * 4;
        asm volatile("red.global.add.v4.f32 [%0], {%1, %2, %3, %4};"
                     :: "l"(dst), "f"(p.x * v), "f"(p.y * v), "f"(p.z * v), "f"(p.w * v)
                     : "memory");
    }
}

// ===========================================================================
// bf16-split warp-MMA GEMM v4: 64 KB smem -> 3 blocks/SM.
// W tiles streamed per-iteration from prepacked global (double-buffered),
// A double-buffered. 512 threads / 16 warps (4M x 4N), warp tile 32x32.
// ===========================================================================
__device__ __forceinline__ uint32_t smem_u32(const void* p) {
    uint32_t a;
    asm("{ .reg .u64 t; cvta.to.shared.u64 t, %1; cvt.u32.u64 %0, t; }"
        : "=r"(a) : "l"(p));
    return a;
}
__device__ __forceinline__ void ldmatrix4(uint32_t* r, uint32_t addr) {
    asm volatile("ldmatrix.sync.aligned.m8n8.x4.shared.b16 {%0,%1,%2,%3}, [%4];"
                 : "=r"(r[0]), "=r"(r[1]), "=r"(r[2]), "=r"(r[3]) : "r"(addr));
}
__device__ __forceinline__ void mma_bf16(float* d, const uint32_t* a,
                                         uint32_t b0, uint32_t b1) {
    asm volatile("mma.sync.aligned.m16n8k16.row.col.f32.bf16.bf16.f32 "
                 "{%0,%1,%2,%3},{%4,%5,%6,%7},{%8,%9},{%0,%1,%2,%3};"
                 : "+f"(d[0]), "+f"(d[1]), "+f"(d[2]), "+f"(d[3])
                 : "r"(a[0]), "r"(a[1]), "r"(a[2]), "r"(a[3]), "r"(b0), "r"(b1));
}

#define GT       512
#define SM_A     0                 // stage s: s*16384; hi +0, lo +8192
#define SM_W     32768             // stage s: 32768 + s*16384; hi +0, lo +8192
#define SM_TOTAL 65536             // 64 KB

__global__ __launch_bounds__(GT) void gemm_mma_kernel(
    const float* __restrict__ A0, const float* __restrict__ A1,
    float* __restrict__ C)
{
    extern __shared__ __align__(128) char smem[];
    const uint32_t sb = smem_u32(smem);

    const int t    = threadIdx.x;
    const int lane = t & 31;
    const int wid  = t >> 5;
    const int warpM = (wid & 3) * 32;
    const int warpN = (wid >> 2) * 32;
    const int blockRow = blockIdx.x * 128;

    const int lrow = t >> 2;
    const int lq   = t & 3;
    const int grow = blockRow + lrow;
    const float* asrc = nullptr;
    if (grow < N_NODE)      asrc = A0 + (size_t)grow * NFEAT;
    else if (grow < N_TOT)  asrc = A1 + (size_t)(grow - N_NODE) * NFEAT;

    const int l15 = lane & 15;
    const int lk  = lane >> 4;

    float acc[2][4][4];
#pragma unroll
    for (int mt = 0; mt < 2; mt++)
#pragma unroll
        for (int nt = 0; nt < 4; nt++)
#pragma unroll
            for (int i = 0; i < 4; i++) acc[mt][nt][i] = 0.f;

    // ---- prologue: W tile 0 -> stage 0, A tile 0 -> stage 0 ----
    {
        uint4* dh = (uint4*)(smem + SM_W);
        uint4* dl = (uint4*)(smem + SM_W + 8192);
        dh[t] = g_Whi_pk[t];
        dl[t] = g_Wlo_pk[t];
    }
    float4 pa[2];
#pragma unroll
    for (int i = 0; i < 2; i++)
        pa[i] = asrc ? __ldg((const float4*)(asrc + lq * 8) + i)
                     : make_float4(0.f, 0.f, 0.f, 0.f);
    {
        uint32_t hp[4], lp[4];
        split_pack8(pa, hp, lp);
        char* hB = smem + SM_A;
        char* lB = smem + SM_A + 8192;
        int ch = lq ^ (lrow & 3);
        *(uint4*)(hB + lrow * 64 + ch * 16) = make_uint4(hp[0], hp[1], hp[2], hp[3]);
        *(uint4*)(lB + lrow * 64 + ch * 16) = make_uint4(lp[0], lp[1], lp[2], lp[3]);
    }
    __syncthreads();

    for (int ki = 0; ki < 8; ki++) {
        const int st  = ki & 1;
        const int nst = (ki + 1) & 1;

        if (ki < 7) {
            // prefetch next A (regs) + next W tile (smem next stage)
            const int kk = (ki + 1) * 32;
#pragma unroll
            for (int i = 0; i < 2; i++)
                pa[i] = asrc ? __ldg((const float4*)(asrc + kk + lq * 8) + i)
                             : make_float4(0.f, 0.f, 0.f, 0.f);
            uint4* dh = (uint4*)(smem + SM_W + nst * 16384);
            uint4* dl = (uint4*)(smem + SM_W + nst * 16384 + 8192);
            dh[t] = g_Whi_pk[(ki + 1) * 512 + t];
            dl[t] = g_Wlo_pk[(ki + 1) * 512 + t];
        }

        const uint32_t aHi = sb + SM_A + (uint32_t)st * 16384;
        const uint32_t aLo = aHi + 8192;
        const uint32_t wHi = sb + SM_W + (uint32_t)st * 16384;
        const uint32_t wLo = wHi + 8192;

#pragma unroll
        for (int ks = 0; ks < 2; ks++) {
            uint32_t ah[2][4], al[2][4];
#pragma unroll
            for (int mt = 0; mt < 2; mt++) {
                int r  = warpM + mt * 16 + l15;
                int ch = ks * 2 + lk;
                uint32_t off = (uint32_t)(r * 64) + (uint32_t)((ch ^ (r & 3)) << 4);
                ldmatrix4(ah[mt], aHi + off);
                ldmatrix4(al[mt], aLo + off);
            }
#pragma unroll
            for (int np = 0; np < 2; np++) {
                int rn = warpN + np * 16 + l15;
                int ch = ks * 2 + lk;
                uint32_t off = (uint32_t)(rn * 64) + (uint32_t)((ch ^ (rn & 3)) << 4);
                uint32_t bh[4], bl[4];
                ldmatrix4(bh, wHi + off);
                ldmatrix4(bl, wLo + off);
#pragma unroll
                for (int sub = 0; sub < 2; sub++) {
                    uint32_t bh0 = bh[sub], bh1 = bh[sub + 2];
                    uint32_t bl0 = bl[sub], bl1 = bl[sub + 2];
                    int nt = np * 2 + sub;
#pragma unroll
                    for (int mt = 0; mt < 2; mt++) {
                        float* d = acc[mt][nt];
                        mma_bf16(d, al[mt], bh0, bh1);
                        mma_bf16(d, ah[mt], bl0, bl1);
                        mma_bf16(d, ah[mt], bh0, bh1);
                    }
                }
            }
        }

        if (ki < 7) {
            uint32_t hp[4], lp[4];
            split_pack8(pa, hp, lp);
            char* hB = smem + SM_A + nst * 16384;
            char* lB = hB + 8192;
            int ch = lq ^ (lrow & 3);
            *(uint4*)(hB + lrow * 64 + ch * 16) = make_uint4(hp[0], hp[1], hp[2], hp[3]);
            *(uint4*)(lB + lrow * 64 + ch * 16) = make_uint4(lp[0], lp[1], lp[2], lp[3]);
        }
        __syncthreads();
    }

    // ---- epilogue: fp32 x1 + fp16 copy ----
    const int erow = blockRow + warpM + (lane >> 2);
    const int ecol0 = (lane & 3) * 2;
#pragma unroll
    for (int mt = 0; mt < 2; mt++) {
        int r0 = erow + mt * 16;
#pragma unroll
        for (int nt = 0; nt < 4; nt++) {
            const float* d = acc[mt][nt];
            int col = warpN + nt * 8 + ecol0;
            if (r0 < N_TOT) {
                *(float2*)(C + (size_t)r0 * NDIM + col) = make_float2(d[0], d[1]);
                *(__half2*)(g_x1h + (size_t)r0 * NDIM + col) =
                    __floats2half2_rn(d[0], d[1]);
            }
            if (r0 + 8 < N_TOT) {
                *(float2*)(C + (size_t)(r0 + 8) * NDIM + col) = make_float2(d[2], d[3]);
                *(__half2*)(g_x1h + (size_t)(r0 + 8) * NDIM + col) =
                    __floats2half2_rn(d[2], d[3]);
            }
        }
    }
}

// ===========================================================================
extern "C" void kernel_launch(void* const* d_in, const int* in_sizes, int n_in,
                              void* d_out, int out_size)
{
    const float* emb_node  = (const float*)d_in[0];
    const float* emb_attri = (const float*)d_in[1];
    const float* W1        = (const float*)d_in[2];
    const int*   adj_row   = (const int*)d_in[3];
    const int*   adj_col   = (const int*)d_in[4];
    const float* adj_val   = (const float*)d_in[5];
    const int*   adj2_row  = (const int*)d_in[6];
    const int*   adj2_col  = (const int*)d_in[7];
    const float* adj2_val  = (const float*)d_in[8];

    float* out = (float*)d_out;
    float* x1 = out;
    float* x2 = out + (size_t)N_TOT * NDIM;
    float* x3 = x2  + (size_t)N_TOT * NDIM;

    const int E = in_sizes[3];

    static cudaStream_t s2 = nullptr;
    static cudaEvent_t evFork = nullptr, evJoin = nullptr;
    if (!s2) {
        cudaStreamCreateWithFlags(&s2, cudaStreamNonBlocking);
        cudaEventCreateWithFlags(&evFork, cudaEventDisableTiming);
        cudaEventCreateWithFlags(&evJoin, cudaEventDisableTiming);
        cudaFuncSetAttribute(gemm_mma_kernel,
                             cudaFuncAttributeMaxDynamicSharedMemorySize, SM_TOTAL);
    }

    zero_cnt_kernel<<<208, 256>>>(W1);

    cudaEventRecord(evFork, 0);
    cudaStreamWaitEvent(s2, evFork, 0);

    int perAdj = (E + 7) / 8;
    int pblocks = (2 * perAdj + 255) / 256;
    place_kernel<<<pblocks, 256, 0, s2>>>(adj_row,  adj_col,  adj_val,
                                          adj2_row, adj2_col, adj2_val, E, perAdj);

    gemm_mma_kernel<<<(N_TOT + 127) / 128, GT, SM_TOTAL>>>(emb_node, emb_attri, x1);

    cudaEventRecord(evJoin, s2);
    cudaStreamWaitEvent(0, evJoin, 0);

    spmm_kernel<<<6375, 256>>>(x2, x3);

    spill_kernel<<<8, 256>>>(x1, x2, x3);
}

// round 14
// speedup vs baseline: 1.1195x; 1.1195x over previous
#include <cuda_runtime.h>
#include <cuda_fp16.h>
#include <cstdint>

#define N_NODE 100000
#define N_TOT  102000
#define NFEAT  256
#define NDIM   128
#define CAP    64
#define SPILL_MAX 8192

typedef unsigned long long u64;

// ===========================================================================
// Device scratch
// ===========================================================================
__device__ int  g_cnt[2][N_TOT];
__device__ u64  g_rec[2][(size_t)N_TOT * CAP];
__device__ int  g_spill_cnt;
__device__ int4 g_spill[SPILL_MAX];
__device__ __align__(16) uint4 g_Whi_pk[4096];   // 64 KB prepacked W hi (fp16)
__device__ __align__(16) uint4 g_Wlo_pk[4096];   // 64 KB prepacked W lo (fp16)
__device__ __align__(16) __half g_x1h[(size_t)N_TOT * NDIM];  // 26 MB fp16 x1

// ---------------------------------------------------------------------------
// fp16 split helpers
// ---------------------------------------------------------------------------
// 16 fp32 -> 8 words hi + 8 words lo (fp16 pairs)
__device__ __forceinline__ void split_pack16h(const float4* v, uint32_t* hp, uint32_t* lp) {
    const float* f = (const float*)v;
#pragma unroll
    for (int i = 0; i < 8; i++) {
        __half h0 = __float2half_rn(f[2*i]);
        __half h1 = __float2half_rn(f[2*i+1]);
        __half l0 = __float2half_rn(f[2*i]   - __half2float(h0));
        __half l1 = __float2half_rn(f[2*i+1] - __half2float(h1));
        hp[i] = (uint32_t)__half_as_ushort(h0) | ((uint32_t)__half_as_ushort(h1) << 16);
        lp[i] = (uint32_t)__half_as_ushort(l0) | ((uint32_t)__half_as_ushort(l1) << 16);
    }
}
// 8 fp32 -> 4 words hi only (fp16 pairs)
__device__ __forceinline__ void pack8h(const float4* v, uint32_t* hp) {
    const float* f = (const float*)v;
#pragma unroll
    for (int i = 0; i < 4; i++) {
        __half h0 = __float2half_rn(f[2*i]);
        __half h1 = __float2half_rn(f[2*i+1]);
        hp[i] = (uint32_t)__half_as_ushort(h0) | ((uint32_t)__half_as_ushort(h1) << 16);
    }
}

// ---------------------------------------------------------------------------
// zero counters + (block 0) prepack W (fp16 hi/lo, swizzled tile layout)
// ---------------------------------------------------------------------------
__global__ void zero_cnt_kernel(const float* __restrict__ W) {
    int i = blockIdx.x * blockDim.x + threadIdx.x;
    int n = 2 * N_TOT;
    int stride = gridDim.x * blockDim.x;
    for (int j = i; j < n; j += stride)
        ((int*)g_cnt)[j] = 0;
    if (i == 0) g_spill_cnt = 0;

    if (blockIdx.x == 0) {
        const int t = threadIdx.x;       // 256 threads: (row, half)
        const int r = t >> 1;
        const int half = t & 1;
        const float* wrow = W + (size_t)r * NFEAT;
        char* hB = (char*)g_Whi_pk;
        char* lB = (char*)g_Wlo_pk;
        for (int ki = 0; ki < 8; ki++) {
            float4 v[4];
#pragma unroll
            for (int q = 0; q < 4; q++)
                v[q] = __ldg((const float4*)(wrow + ki * 32 + half * 16) + q);
            uint32_t hp[8], lp[8];
            split_pack16h(v, hp, lp);
            int sw = r & 3;
#pragma unroll
            for (int cc = 0; cc < 2; cc++) {
                int ch = (half * 2 + cc) ^ sw;
                int off = ki * 8192 + r * 64 + ch * 16;
                *(uint4*)(hB + off) = make_uint4(hp[cc*4], hp[cc*4+1], hp[cc*4+2], hp[cc*4+3]);
                *(uint4*)(lB + off) = make_uint4(lp[cc*4], lp[cc*4+1], lp[cc*4+2], lp[cc*4+3]);
            }
        }
    }
}

// ---------------------------------------------------------------------------
// ELL placement (R12 version: plain col in record low32... keep pre-scaled? R13
// showed neutral; keep R12's plain col to match proven spmm binary: use col*NDIM
// — actually R13 spmm was equal-or-slightly-better; retain pre-scaled col.)
// ---------------------------------------------------------------------------
__global__ __launch_bounds__(256) void place_kernel(
    const int* __restrict__ erow1, const int* __restrict__ ecol1, const float* __restrict__ eval1,
    const int* __restrict__ erow2, const int* __restrict__ ecol2, const float* __restrict__ eval2,
    int E, int perAdj)
{
    int idx = blockIdx.x * blockDim.x + threadIdx.x;
    int a = 0;
    if (idx >= perAdj) { a = 1; idx -= perAdj; if (idx >= perAdj) return; }
    const int*   erow = a ? erow2 : erow1;
    const int*   ecol = a ? ecol2 : ecol1;
    const float* eval = a ? eval2 : eval1;
    u64* rec = g_rec[a];
    int* cnt = g_cnt[a];

    int e0 = idx * 8;
    int nn = (e0 + 8 <= E) ? 8 : (E - e0);
    if (nn <= 0) return;

    int rr[8], cc[8]; float vv[8];
#pragma unroll
    for (int q = 0; q < 2; q++) {
        if (e0 + q * 4 + 4 <= E) {
            int4   r4 = *(const int4*)(erow + e0 + q * 4);
            int4   c4 = *(const int4*)(ecol + e0 + q * 4);
            float4 v4 = *(const float4*)(eval + e0 + q * 4);
            rr[q*4+0] = r4.x; rr[q*4+1] = r4.y; rr[q*4+2] = r4.z; rr[q*4+3] = r4.w;
            cc[q*4+0] = c4.x; cc[q*4+1] = c4.y; cc[q*4+2] = c4.z; cc[q*4+3] = c4.w;
            vv[q*4+0] = v4.x; vv[q*4+1] = v4.y; vv[q*4+2] = v4.z; vv[q*4+3] = v4.w;
        } else {
            for (int i = q * 4; i < nn; i++) {
                rr[i] = __ldg(erow + e0 + i);
                cc[i] = __ldg(ecol + e0 + i);
                vv[i] = __ldg(eval + e0 + i);
            }
        }
    }

    int pos[8];
#pragma unroll
    for (int i = 0; i < 8; i++)
        if (i < nn) pos[i] = atomicAdd(&cnt[rr[i]], 1);

#pragma unroll
    for (int i = 0; i < 8; i++) {
        if (i < nn) {
            u64 r8 = (u64)(unsigned)(cc[i] * NDIM)
                   | ((u64)__float_as_uint(vv[i]) << 32);
            if (pos[i] < CAP) {
                rec[(size_t)rr[i] * CAP + pos[i]] = r8;
            } else {
                int s = atomicAdd(&g_spill_cnt, 1);
                if (s < SPILL_MAX)
                    g_spill[s] = make_int4(rr[i] | (a << 30), cc[i],
                                           (int)__float_as_uint(vv[i]), 0);
            }
        }
    }
}

// ---------------------------------------------------------------------------
// SpMM v4b (R13 binary: fp16 gathers, MLP=8, pre-scaled col)
// ---------------------------------------------------------------------------
__global__ __launch_bounds__(256) void spmm_kernel(
    float* __restrict__ x2, float* __restrict__ x3)
{
    const int lane  = threadIdx.x & 31;
    const int warp0 = (int)(((size_t)blockIdx.x * blockDim.x + threadIdx.x) >> 5);
    const int nw    = (gridDim.x * blockDim.x) >> 5;
    const __half* xh = g_x1h;

    for (int gw = warp0; gw < 2 * N_TOT; gw += nw) {
        const int a = (gw >= N_TOT) ? 1 : 0;
        const int r = a ? (gw - N_TOT) : gw;

        int m = g_cnt[a][r];
        if (m > CAP) m = CAP;
        const u64* rp = g_rec[a] + (size_t)r * CAP;

        u64 myrec = 0;
        if (lane < m) myrec = __ldg(rp + lane);

        float4 accA = make_float4(0.f, 0.f, 0.f, 0.f);
        float4 accB = make_float4(0.f, 0.f, 0.f, 0.f);
        const int m1 = (m < 32) ? m : 32;
        int k = 0;

        for (; k + 8 <= m1; k += 8) {
            uint2 u[8]; float v[8];
#pragma unroll
            for (int i = 0; i < 8; i++) {
                u64 q = __shfl_sync(0xffffffffu, myrec, k + i);
                v[i] = __uint_as_float((unsigned)(q >> 32));
                u[i] = __ldg((const uint2*)(xh + (unsigned)q) + lane);
            }
#pragma unroll
            for (int i = 0; i < 8; i++) {
                float2 f01 = __half22float2(*(const __half2*)&u[i].x);
                float2 f23 = __half22float2(*(const __half2*)&u[i].y);
                float4* A = (i & 1) ? &accB : &accA;
                A->x = fmaf(v[i], f01.x, A->x);
                A->y = fmaf(v[i], f01.y, A->y);
                A->z = fmaf(v[i], f23.x, A->z);
                A->w = fmaf(v[i], f23.y, A->w);
            }
        }
        for (; k < m1; k++) {
            u64 q = __shfl_sync(0xffffffffu, myrec, k);
            float v = __uint_as_float((unsigned)(q >> 32));
            uint2 u = __ldg((const uint2*)(xh + (unsigned)q) + lane);
            float2 f01 = __half22float2(*(const __half2*)&u.x);
            float2 f23 = __half22float2(*(const __half2*)&u.y);
            accA.x = fmaf(v, f01.x, accA.x);
            accA.y = fmaf(v, f01.y, accA.y);
            accA.z = fmaf(v, f23.x, accA.z);
            accA.w = fmaf(v, f23.y, accA.w);
        }
        for (; k < m; k++) {
            u64 q = __ldg(rp + k);
            float v = __uint_as_float((unsigned)(q >> 32));
            uint2 u = __ldg((const uint2*)(xh + (unsigned)q) + lane);
            float2 f01 = __half22float2(*(const __half2*)&u.x);
            float2 f23 = __half22float2(*(const __half2*)&u.y);
            accA.x = fmaf(v, f01.x, accA.x);
            accA.y = fmaf(v, f01.y, accA.y);
            accA.z = fmaf(v, f23.x, accA.z);
            accA.w = fmaf(v, f23.y, accA.w);
        }

        float4 acc;
        acc.x = accA.x + accB.x; acc.y = accA.y + accB.y;
        acc.z = accA.z + accB.z; acc.w = accA.w + accB.w;
        float* outp = (a ? x3 : x2) + (size_t)r * NDIM;
        ((float4*)outp)[lane] = acc;
    }
}

__global__ __launch_bounds__(256) void spill_kernel(
    const float* __restrict__ x1, float* __restrict__ x2, float* __restrict__ x3)
{
    int nspill = g_spill_cnt;
    if (nspill > SPILL_MAX) nspill = SPILL_MAX;
    int lane = threadIdx.x & 31;
    int warp = (blockIdx.x * blockDim.x + threadIdx.x) >> 5;
    int nwarps = (gridDim.x * blockDim.x) >> 5;
    for (int s = warp; s < nspill; s += nwarps) {
        int4 e = g_spill[s];
        int a = (e.x >> 30) & 1;
        int r = e.x & 0x3fffffff;
        float v = __uint_as_float((unsigned)e.z);
        float4 p = __ldg((const float4*)(x1 + (size_t)e.y * NDIM) + lane);
        float* dst = (a ? x3 : x2) + (size_t)r * NDIM + lane * 4;
        asm volatile("red.global.add.v4.f32 [%0], {%1, %2, %3, %4};"
                     :: "l"(dst), "f"(p.x * v), "f"(p.y * v), "f"(p.z * v), "f"(p.w * v)
                     : "memory");
    }
}

// ===========================================================================
// fp16 asymmetric-split warp-MMA GEMM v5:
// D = Ahi*Whi + Ahi*Wlo   (dropped Alo*W ~ 2^-12 rel)
// 2 MMA passes (33% fewer HMMAs). W hi+lo resident (128 KB), A hi only,
// double-buffered (2 x 8 KB). 512 threads / 16 warps (4M x 4N), warp 32x32.
// ===========================================================================
__device__ __forceinline__ uint32_t smem_u32(const void* p) {
    uint32_t a;
    asm("{ .reg .u64 t; cvta.to.shared.u64 t, %1; cvt.u32.u64 %0, t; }"
        : "=r"(a) : "l"(p));
    return a;
}
__device__ __forceinline__ void ldmatrix4(uint32_t* r, uint32_t addr) {
    asm volatile("ldmatrix.sync.aligned.m8n8.x4.shared.b16 {%0,%1,%2,%3}, [%4];"
                 : "=r"(r[0]), "=r"(r[1]), "=r"(r[2]), "=r"(r[3]) : "r"(addr));
}
__device__ __forceinline__ void mma_f16(float* d, const uint32_t* a,
                                        uint32_t b0, uint32_t b1) {
    asm volatile("mma.sync.aligned.m16n8k16.row.col.f32.f16.f16.f32 "
                 "{%0,%1,%2,%3},{%4,%5,%6,%7},{%8,%9},{%0,%1,%2,%3};"
                 : "+f"(d[0]), "+f"(d[1]), "+f"(d[2]), "+f"(d[3])
                 : "r"(a[0]), "r"(a[1]), "r"(a[2]), "r"(a[3]), "r"(b0), "r"(b1));
}

#define GT       512
#define SM_WHI   0
#define SM_WLO   65536
#define SM_A     131072            // stage s: +s*8192 (hi only)
#define SM_TOTAL 147456            // 144 KB

__global__ __launch_bounds__(GT, 1) void gemm_mma_kernel(
    const float* __restrict__ A0, const float* __restrict__ A1,
    float* __restrict__ C)
{
    extern __shared__ __align__(128) char smem[];
    const uint32_t sb = smem_u32(smem);

    const int t    = threadIdx.x;
    const int lane = t & 31;
    const int wid  = t >> 5;
    const int warpM = (wid & 3) * 32;
    const int warpN = (wid >> 2) * 32;
    const int blockRow = blockIdx.x * 128;

    // ---- copy prepacked W into smem (8 uint4 per thread per half) ----
    {
        uint4* dh = (uint4*)(smem + SM_WHI);
        uint4* dl = (uint4*)(smem + SM_WLO);
#pragma unroll
        for (int i = 0; i < 8; i++) {
            dh[t + i * GT] = g_Whi_pk[t + i * GT];
            dl[t + i * GT] = g_Wlo_pk[t + i * GT];
        }
    }

    // loader mapping: 4 threads per row, 8 floats -> 8 fp16 (one 16B chunk)
    const int lrow = t >> 2;
    const int lq   = t & 3;
    const int grow = blockRow + lrow;
    const float* asrc = nullptr;
    if (grow < N_NODE)      asrc = A0 + (size_t)grow * NFEAT;
    else if (grow < N_TOT)  asrc = A1 + (size_t)(grow - N_NODE) * NFEAT;

    const int l15 = lane & 15;
    const int lk  = lane >> 4;

    float acc[2][4][4];
#pragma unroll
    for (int mt = 0; mt < 2; mt++)
#pragma unroll
        for (int nt = 0; nt < 4; nt++)
#pragma unroll
            for (int i = 0; i < 4; i++) acc[mt][nt][i] = 0.f;

    // ---- prologue: A tile 0 -> stage 0 ----
    float4 pa[2];
#pragma unroll
    for (int i = 0; i < 2; i++)
        pa[i] = asrc ? __ldg((const float4*)(asrc + lq * 8) + i)
                     : make_float4(0.f, 0.f, 0.f, 0.f);
    {
        uint32_t hp[4];
        pack8h(pa, hp);
        char* hB = smem + SM_A;
        int ch = lq ^ (lrow & 3);
        *(uint4*)(hB + lrow * 64 + ch * 16) = make_uint4(hp[0], hp[1], hp[2], hp[3]);
    }
    __syncthreads();

    // ---- main pipeline ----
    for (int ki = 0; ki < 8; ki++) {
        if (ki < 7) {
            const int kk = (ki + 1) * 32;
#pragma unroll
            for (int i = 0; i < 2; i++)
                pa[i] = asrc ? __ldg((const float4*)(asrc + kk + lq * 8) + i)
                             : make_float4(0.f, 0.f, 0.f, 0.f);
        }

        const uint32_t aHi = sb + SM_A + (uint32_t)(ki & 1) * 8192;
        const uint32_t wHi = sb + SM_WHI + (uint32_t)ki * 8192;
        const uint32_t wLo = sb + SM_WLO + (uint32_t)ki * 8192;

#pragma unroll
        for (int ks = 0; ks < 2; ks++) {
            uint32_t ah[2][4];
#pragma unroll
            for (int mt = 0; mt < 2; mt++) {
                int r  = warpM + mt * 16 + l15;
                int ch = ks * 2 + lk;
                uint32_t off = (uint32_t)(r * 64) + (uint32_t)((ch ^ (r & 3)) << 4);
                ldmatrix4(ah[mt], aHi + off);
            }
#pragma unroll
            for (int np = 0; np < 2; np++) {
                int rn = warpN + np * 16 + l15;
                int ch = ks * 2 + lk;
                uint32_t off = (uint32_t)(rn * 64) + (uint32_t)((ch ^ (rn & 3)) << 4);
                uint32_t bh[4], bl[4];
                ldmatrix4(bh, wHi + off);
                ldmatrix4(bl, wLo + off);
#pragma unroll
                for (int sub = 0; sub < 2; sub++) {
                    uint32_t bh0 = bh[sub], bh1 = bh[sub + 2];
                    uint32_t bl0 = bl[sub], bl1 = bl[sub + 2];
                    int nt = np * 2 + sub;
#pragma unroll
                    for (int mt = 0; mt < 2; mt++) {
                        float* d = acc[mt][nt];
                        mma_f16(d, ah[mt], bl0, bl1);   // hi*lo (small first)
                        mma_f16(d, ah[mt], bh0, bh1);   // hi*hi
                    }
                }
            }
        }

        if (ki < 7) {
            uint32_t hp[4];
            pack8h(pa, hp);
            char* hB = smem + SM_A + ((ki + 1) & 1) * 8192;
            int ch = lq ^ (lrow & 3);
            *(uint4*)(hB + lrow * 64 + ch * 16) = make_uint4(hp[0], hp[1], hp[2], hp[3]);
        }
        __syncthreads();
    }

    // ---- epilogue: fp32 x1 + fp16 copy ----
    const int erow = blockRow + warpM + (lane >> 2);
    const int ecol0 = (lane & 3) * 2;
#pragma unroll
    for (int mt = 0; mt < 2; mt++) {
        int r0 = erow + mt * 16;
#pragma unroll
        for (int nt = 0; nt < 4; nt++) {
            const float* d = acc[mt][nt];
            int col = warpN + nt * 8 + ecol0;
            if (r0 < N_TOT) {
                *(float2*)(C + (size_t)r0 * NDIM + col) = make_float2(d[0], d[1]);
                *(__half2*)(g_x1h + (size_t)r0 * NDIM + col) =
                    __floats2half2_rn(d[0], d[1]);
            }
            if (r0 + 8 < N_TOT) {
                *(float2*)(C + (size_t)(r0 + 8) * NDIM + col) = make_float2(d[2], d[3]);
                *(__half2*)(g_x1h + (size_t)(r0 + 8) * NDIM + col) =
                    __floats2half2_rn(d[2], d[3]);
            }
        }
    }
}

// ===========================================================================
extern "C" void kernel_launch(void* const* d_in, const int* in_sizes, int n_in,
                              void* d_out, int out_size)
{
    const float* emb_node  = (const float*)d_in[0];
    const float* emb_attri = (const float*)d_in[1];
    const float* W1        = (const float*)d_in[2];
    const int*   adj_row   = (const int*)d_in[3];
    const int*   adj_col   = (const int*)d_in[4];
    const float* adj_val   = (const float*)d_in[5];
    const int*   adj2_row  = (const int*)d_in[6];
    const int*   adj2_col  = (const int*)d_in[7];
    const float* adj2_val  = (const float*)d_in[8];

    float* out = (float*)d_out;
    float* x1 = out;
    float* x2 = out + (size_t)N_TOT * NDIM;
    float* x3 = x2  + (size_t)N_TOT * NDIM;

    const int E = in_sizes[3];

    static cudaStream_t s2 = nullptr;
    static cudaEvent_t evFork = nullptr, evJoin = nullptr;
    if (!s2) {
        cudaStreamCreateWithFlags(&s2, cudaStreamNonBlocking);
        cudaEventCreateWithFlags(&evFork, cudaEventDisableTiming);
        cudaEventCreateWithFlags(&evJoin, cudaEventDisableTiming);
        cudaFuncSetAttribute(gemm_mma_kernel,
                             cudaFuncAttributeMaxDynamicSharedMemorySize, SM_TOTAL);
    }

    zero_cnt_kernel<<<208, 256>>>(W1);

    cudaEventRecord(evFork, 0);
    cudaStreamWaitEvent(s2, evFork, 0);

    int perAdj = (E + 7) / 8;
    int pblocks = (2 * perAdj + 255) / 256;
    place_kernel<<<pblocks, 256, 0, s2>>>(adj_row,  adj_col,  adj_val,
                                          adj2_row, adj2_col, adj2_val, E, perAdj);

    gemm_mma_kernel<<<(N_TOT + 127) / 128, GT, SM_TOTAL>>>(emb_node, emb_attri, x1);

    cudaEventRecord(evJoin, s2);
    cudaStreamWaitEvent(0, evJoin, 0);

    spmm_kernel<<<6375, 256>>>(x2, x3);

    spill_kernel<<<8, 256>>>(x1, x2, x3);
}

// round 15
// speedup vs baseline: 1.1364x; 1.0151x over previous
#include <cuda_runtime.h>
#include <cuda_fp16.h>
#include <cstdint>

#define N_NODE 100000
#define N_TOT  102000
#define NFEAT  256
#define NDIM   128
#define CAP    64
#define SPILL_MAX 8192

typedef unsigned long long u64;

// ===========================================================================
// Device scratch
// ===========================================================================
__device__ int  g_cnt[2][N_TOT];
__device__ u64  g_rec[2][(size_t)N_TOT * CAP];   // low32: col*NDIM, high32: val
__device__ int  g_spill_cnt;
__device__ int4 g_spill[SPILL_MAX];
__device__ __align__(16) uint4 g_Whi_pk[4096];   // 64 KB prepacked W (fp16)
__device__ __align__(16) __half g_x1h[(size_t)N_TOT * NDIM];  // 26 MB fp16 x1

// ---------------------------------------------------------------------------
// 16 fp32 -> 8 fp16x2 words
__device__ __forceinline__ void pack16h(const float4* v, uint32_t* hp) {
    const float* f = (const float*)v;
#pragma unroll
    for (int i = 0; i < 8; i++) {
        __half h0 = __float2half_rn(f[2*i]);
        __half h1 = __float2half_rn(f[2*i+1]);
        hp[i] = (uint32_t)__half_as_ushort(h0) | ((uint32_t)__half_as_ushort(h1) << 16);
    }
}
// 8 fp32 -> 4 fp16x2 words
__device__ __forceinline__ void pack8h(const float4* v, uint32_t* hp) {
    const float* f = (const float*)v;
#pragma unroll
    for (int i = 0; i < 4; i++) {
        __half h0 = __float2half_rn(f[2*i]);
        __half h1 = __float2half_rn(f[2*i+1]);
        hp[i] = (uint32_t)__half_as_ushort(h0) | ((uint32_t)__half_as_ushort(h1) << 16);
    }
}

// ---------------------------------------------------------------------------
// zero counters + (block 0) prepack W (fp16, swizzled tile layout)
// ---------------------------------------------------------------------------
__global__ void zero_cnt_kernel(const float* __restrict__ W) {
    int i = blockIdx.x * blockDim.x + threadIdx.x;
    int n = 2 * N_TOT;
    int stride = gridDim.x * blockDim.x;
    for (int j = i; j < n; j += stride)
        ((int*)g_cnt)[j] = 0;
    if (i == 0) g_spill_cnt = 0;

    if (blockIdx.x == 0) {
        const int t = threadIdx.x;       // 256 threads: (row, half)
        const int r = t >> 1;
        const int half = t & 1;
        const float* wrow = W + (size_t)r * NFEAT;
        char* hB = (char*)g_Whi_pk;
        for (int ki = 0; ki < 8; ki++) {
            float4 v[4];
#pragma unroll
            for (int q = 0; q < 4; q++)
                v[q] = __ldg((const float4*)(wrow + ki * 32 + half * 16) + q);
            uint32_t hp[8];
            pack16h(v, hp);
            int sw = r & 3;
#pragma unroll
            for (int cc = 0; cc < 2; cc++) {
                int ch = (half * 2 + cc) ^ sw;
                int off = ki * 8192 + r * 64 + ch * 16;
                *(uint4*)(hB + off) = make_uint4(hp[cc*4], hp[cc*4+1], hp[cc*4+2], hp[cc*4+3]);
            }
        }
    }
}

// ---------------------------------------------------------------------------
// ELL placement (unchanged; records carry col*NDIM)
// ---------------------------------------------------------------------------
__global__ __launch_bounds__(256) void place_kernel(
    const int* __restrict__ erow1, const int* __restrict__ ecol1, const float* __restrict__ eval1,
    const int* __restrict__ erow2, const int* __restrict__ ecol2, const float* __restrict__ eval2,
    int E, int perAdj)
{
    int idx = blockIdx.x * blockDim.x + threadIdx.x;
    int a = 0;
    if (idx >= perAdj) { a = 1; idx -= perAdj; if (idx >= perAdj) return; }
    const int*   erow = a ? erow2 : erow1;
    const int*   ecol = a ? ecol2 : ecol1;
    const float* eval = a ? eval2 : eval1;
    u64* rec = g_rec[a];
    int* cnt = g_cnt[a];

    int e0 = idx * 8;
    int nn = (e0 + 8 <= E) ? 8 : (E - e0);
    if (nn <= 0) return;

    int rr[8], cc[8]; float vv[8];
#pragma unroll
    for (int q = 0; q < 2; q++) {
        if (e0 + q * 4 + 4 <= E) {
            int4   r4 = *(const int4*)(erow + e0 + q * 4);
            int4   c4 = *(const int4*)(ecol + e0 + q * 4);
            float4 v4 = *(const float4*)(eval + e0 + q * 4);
            rr[q*4+0] = r4.x; rr[q*4+1] = r4.y; rr[q*4+2] = r4.z; rr[q*4+3] = r4.w;
            cc[q*4+0] = c4.x; cc[q*4+1] = c4.y; cc[q*4+2] = c4.z; cc[q*4+3] = c4.w;
            vv[q*4+0] = v4.x; vv[q*4+1] = v4.y; vv[q*4+2] = v4.z; vv[q*4+3] = v4.w;
        } else {
            for (int i = q * 4; i < nn; i++) {
                rr[i] = __ldg(erow + e0 + i);
                cc[i] = __ldg(ecol + e0 + i);
                vv[i] = __ldg(eval + e0 + i);
            }
        }
    }

    int pos[8];
#pragma unroll
    for (int i = 0; i < 8; i++)
        if (i < nn) pos[i] = atomicAdd(&cnt[rr[i]], 1);

#pragma unroll
    for (int i = 0; i < 8; i++) {
        if (i < nn) {
            u64 r8 = (u64)(unsigned)(cc[i] * NDIM)
                   | ((u64)__float_as_uint(vv[i]) << 32);
            if (pos[i] < CAP) {
                rec[(size_t)rr[i] * CAP + pos[i]] = r8;
            } else {
                int s = atomicAdd(&g_spill_cnt, 1);
                if (s < SPILL_MAX)
                    g_spill[s] = make_int4(rr[i] | (a << 30), cc[i],
                                           (int)__float_as_uint(vv[i]), 0);
            }
        }
    }
}

// ---------------------------------------------------------------------------
// SpMM v5: fp16 gathers, MLP=8, occupancy-targeted (min 6 blocks/SM)
// ---------------------------------------------------------------------------
__global__ __launch_bounds__(256, 6) void spmm_kernel(
    float* __restrict__ x2, float* __restrict__ x3)
{
    const int lane  = threadIdx.x & 31;
    const int warp0 = (int)(((size_t)blockIdx.x * blockDim.x + threadIdx.x) >> 5);
    const int nw    = (gridDim.x * blockDim.x) >> 5;
    const __half* xh = g_x1h;

    for (int gw = warp0; gw < 2 * N_TOT; gw += nw) {
        const int a = (gw >= N_TOT) ? 1 : 0;
        const int r = a ? (gw - N_TOT) : gw;

        int m = g_cnt[a][r];
        if (m > CAP) m = CAP;
        const u64* rp = g_rec[a] + (size_t)r * CAP;

        u64 myrec = 0;
        if (lane < m) myrec = __ldg(rp + lane);

        float4 accA = make_float4(0.f, 0.f, 0.f, 0.f);
        float4 accB = make_float4(0.f, 0.f, 0.f, 0.f);
        const int m1 = (m < 32) ? m : 32;
        int k = 0;

        for (; k + 8 <= m1; k += 8) {
            uint2 u[8];
#pragma unroll
            for (int i = 0; i < 8; i++) {
                u64 q = __shfl_sync(0xffffffffu, myrec, k + i);
                u[i] = __ldg((const uint2*)(xh + (unsigned)q) + lane);
            }
#pragma unroll
            for (int i = 0; i < 8; i++) {
                u64 q = __shfl_sync(0xffffffffu, myrec, k + i);
                float v = __uint_as_float((unsigned)(q >> 32));
                float2 f01 = __half22float2(*(const __half2*)&u[i].x);
                float2 f23 = __half22float2(*(const __half2*)&u[i].y);
                float4* A = (i & 1) ? &accB : &accA;
                A->x = fmaf(v, f01.x, A->x);
                A->y = fmaf(v, f01.y, A->y);
                A->z = fmaf(v, f23.x, A->z);
                A->w = fmaf(v, f23.y, A->w);
            }
        }
        for (; k < m1; k++) {
            u64 q = __shfl_sync(0xffffffffu, myrec, k);
            float v = __uint_as_float((unsigned)(q >> 32));
            uint2 u = __ldg((const uint2*)(xh + (unsigned)q) + lane);
            float2 f01 = __half22float2(*(const __half2*)&u.x);
            float2 f23 = __half22float2(*(const __half2*)&u.y);
            accA.x = fmaf(v, f01.x, accA.x);
            accA.y = fmaf(v, f01.y, accA.y);
            accA.z = fmaf(v, f23.x, accA.z);
            accA.w = fmaf(v, f23.y, accA.w);
        }
        for (; k < m; k++) {
            u64 q = __ldg(rp + k);
            float v = __uint_as_float((unsigned)(q >> 32));
            uint2 u = __ldg((const uint2*)(xh + (unsigned)q) + lane);
            float2 f01 = __half22float2(*(const __half2*)&u.x);
            float2 f23 = __half22float2(*(const __half2*)&u.y);
            accA.x = fmaf(v, f01.x, accA.x);
            accA.y = fmaf(v, f01.y, accA.y);
            accA.z = fmaf(v, f23.x, accA.z);
            accA.w = fmaf(v, f23.y, accA.w);
        }

        float4 acc;
        acc.x = accA.x + accB.x; acc.y = accA.y + accB.y;
        acc.z = accA.z + accB.z; acc.w = accA.w + accB.w;
        float* outp = (a ? x3 : x2) + (size_t)r * NDIM;
        ((float4*)outp)[lane] = acc;
    }
}

__global__ __launch_bounds__(256) void spill_kernel(
    const float* __restrict__ x1, float* __restrict__ x2, float* __restrict__ x3)
{
    int nspill = g_spill_cnt;
    if (nspill > SPILL_MAX) nspill = SPILL_MAX;
    int lane = threadIdx.x & 31;
    int warp = (blockIdx.x * blockDim.x + threadIdx.x) >> 5;
    int nwarps = (gridDim.x * blockDim.x) >> 5;
    for (int s = warp; s < nspill; s += nwarps) {
        int4 e = g_spill[s];
        int a = (e.x >> 30) & 1;
        int r = e.x & 0x3fffffff;
        float v = __uint_as_float((unsigned)e.z);
        float4 p = __ldg((const float4*)(x1 + (size_t)e.y * NDIM) + lane);
        float* dst = (a ? x3 : x2) + (size_t)r * NDIM + lane * 4;
        asm volatile("red.global.add.v4.f32 [%0], {%1, %2, %3, %4};"
                     :: "l"(dst), "f"(p.x * v), "f"(p.y * v), "f"(p.z * v), "f"(p.w * v)
                     : "memory");
    }
}

// ===========================================================================
// pure-fp16 warp-MMA GEMM v6: D = fp16(A) * fp16(W), fp32 accum, 1 MMA pass.
// W resident (64 KB), A double-buffered (2 x 8 KB) -> 80 KB, 2 blocks/SM.
// 512 threads / 16 warps (4M x 4N), warp tile 32x32.
// ===========================================================================
__device__ __forceinline__ uint32_t smem_u32(const void* p) {
    uint32_t a;
    asm("{ .reg .u64 t; cvta.to.shared.u64 t, %1; cvt.u32.u64 %0, t; }"
        : "=r"(a) : "l"(p));
    return a;
}
__device__ __forceinline__ void ldmatrix4(uint32_t* r, uint32_t addr) {
    asm volatile("ldmatrix.sync.aligned.m8n8.x4.shared.b16 {%0,%1,%2,%3}, [%4];"
                 : "=r"(r[0]), "=r"(r[1]), "=r"(r[2]), "=r"(r[3]) : "r"(addr));
}
__device__ __forceinline__ void mma_f16(float* d, const uint32_t* a,
                                        uint32_t b0, uint32_t b1) {
    asm volatile("mma.sync.aligned.m16n8k16.row.col.f32.f16.f16.f32 "
                 "{%0,%1,%2,%3},{%4,%5,%6,%7},{%8,%9},{%0,%1,%2,%3};"
                 : "+f"(d[0]), "+f"(d[1]), "+f"(d[2]), "+f"(d[3])
                 : "r"(a[0]), "r"(a[1]), "r"(a[2]), "r"(a[3]), "r"(b0), "r"(b1));
}

#define GT       512
#define SM_WHI   0
#define SM_A     65536             // stage s: +s*8192
#define SM_TOTAL 81920             // 80 KB

__global__ __launch_bounds__(GT) void gemm_mma_kernel(
    const float* __restrict__ A0, const float* __restrict__ A1,
    float* __restrict__ C)
{
    extern __shared__ __align__(128) char smem[];
    const uint32_t sb = smem_u32(smem);

    const int t    = threadIdx.x;
    const int lane = t & 31;
    const int wid  = t >> 5;
    const int warpM = (wid & 3) * 32;
    const int warpN = (wid >> 2) * 32;
    const int blockRow = blockIdx.x * 128;

    // ---- copy prepacked W into smem (8 uint4 per thread) ----
    {
        uint4* dh = (uint4*)(smem + SM_WHI);
#pragma unroll
        for (int i = 0; i < 8; i++)
            dh[t + i * GT] = g_Whi_pk[t + i * GT];
    }

    // loader mapping: 4 threads per row, 8 floats -> 8 fp16 (one 16B chunk)
    const int lrow = t >> 2;
    const int lq   = t & 3;
    const int grow = blockRow + lrow;
    const float* asrc = nullptr;
    if (grow < N_NODE)      asrc = A0 + (size_t)grow * NFEAT;
    else if (grow < N_TOT)  asrc = A1 + (size_t)(grow - N_NODE) * NFEAT;

    const int l15 = lane & 15;
    const int lk  = lane >> 4;

    float acc[2][4][4];
#pragma unroll
    for (int mt = 0; mt < 2; mt++)
#pragma unroll
        for (int nt = 0; nt < 4; nt++)
#pragma unroll
            for (int i = 0; i < 4; i++) acc[mt][nt][i] = 0.f;

    // ---- prologue: A tile 0 -> stage 0 ----
    float4 pa[2];
#pragma unroll
    for (int i = 0; i < 2; i++)
        pa[i] = asrc ? __ldg((const float4*)(asrc + lq * 8) + i)
                     : make_float4(0.f, 0.f, 0.f, 0.f);
    {
        uint32_t hp[4];
        pack8h(pa, hp);
        char* hB = smem + SM_A;
        int ch = lq ^ (lrow & 3);
        *(uint4*)(hB + lrow * 64 + ch * 16) = make_uint4(hp[0], hp[1], hp[2], hp[3]);
    }
    __syncthreads();

    // ---- main pipeline ----
    for (int ki = 0; ki < 8; ki++) {
        if (ki < 7) {
            const int kk = (ki + 1) * 32;
#pragma unroll
            for (int i = 0; i < 2; i++)
                pa[i] = asrc ? __ldg((const float4*)(asrc + kk + lq * 8) + i)
                             : make_float4(0.f, 0.f, 0.f, 0.f);
        }

        const uint32_t aHi = sb + SM_A + (uint32_t)(ki & 1) * 8192;
        const uint32_t wHi = sb + SM_WHI + (uint32_t)ki * 8192;

#pragma unroll
        for (int ks = 0; ks < 2; ks++) {
            uint32_t ah[2][4];
#pragma unroll
            for (int mt = 0; mt < 2; mt++) {
                int r  = warpM + mt * 16 + l15;
                int ch = ks * 2 + lk;
                uint32_t off = (uint32_t)(r * 64) + (uint32_t)((ch ^ (r & 3)) << 4);
                ldmatrix4(ah[mt], aHi + off);
            }
#pragma unroll
            for (int np = 0; np < 2; np++) {
                int rn = warpN + np * 16 + l15;
                int ch = ks * 2 + lk;
                uint32_t off = (uint32_t)(rn * 64) + (uint32_t)((ch ^ (rn & 3)) << 4);
                uint32_t bh[4];
                ldmatrix4(bh, wHi + off);
#pragma unroll
                for (int sub = 0; sub < 2; sub++) {
                    uint32_t bh0 = bh[sub], bh1 = bh[sub + 2];
                    int nt = np * 2 + sub;
#pragma unroll
                    for (int mt = 0; mt < 2; mt++)
                        mma_f16(acc[mt][nt], ah[mt], bh0, bh1);
                }
            }
        }

        if (ki < 7) {
            uint32_t hp[4];
            pack8h(pa, hp);
            char* hB = smem + SM_A + ((ki + 1) & 1) * 8192;
            int ch = lq ^ (lrow & 3);
            *(uint4*)(hB + lrow * 64 + ch * 16) = make_uint4(hp[0], hp[1], hp[2], hp[3]);
        }
        __syncthreads();
    }

    // ---- epilogue: fp32 x1 + fp16 copy ----
    const int erow = blockRow + warpM + (lane >> 2);
    const int ecol0 = (lane & 3) * 2;
#pragma unroll
    for (int mt = 0; mt < 2; mt++) {
        int r0 = erow + mt * 16;
#pragma unroll
        for (int nt = 0; nt < 4; nt++) {
            const float* d = acc[mt][nt];
            int col = warpN + nt * 8 + ecol0;
            if (r0 < N_TOT) {
                *(float2*)(C + (size_t)r0 * NDIM + col) = make_float2(d[0], d[1]);
                *(__half2*)(g_x1h + (size_t)r0 * NDIM + col) =
                    __floats2half2_rn(d[0], d[1]);
            }
            if (r0 + 8 < N_TOT) {
                *(float2*)(C + (size_t)(r0 + 8) * NDIM + col) = make_float2(d[2], d[3]);
                *(__half2*)(g_x1h + (size_t)(r0 + 8) * NDIM + col) =
                    __floats2half2_rn(d[2], d[3]);
            }
        }
    }
}

// ===========================================================================
extern "C" void kernel_launch(void* const* d_in, const int* in_sizes, int n_in,
                              void* d_out, int out_size)
{
    const float* emb_node  = (const float*)d_in[0];
    const float* emb_attri = (const float*)d_in[1];
    const float* W1        = (const float*)d_in[2];
    const int*   adj_row   = (const int*)d_in[3];
    const int*   adj_col   = (const int*)d_in[4];
    const float* adj_val   = (const float*)d_in[5];
    const int*   adj2_row  = (const int*)d_in[6];
    const int*   adj2_col  = (const int*)d_in[7];
    const float* adj2_val  = (const float*)d_in[8];

    float* out = (float*)d_out;
    float* x1 = out;
    float* x2 = out + (size_t)N_TOT * NDIM;
    float* x3 = x2  + (size_t)N_TOT * NDIM;

    const int E = in_sizes[3];

    static cudaStream_t s2 = nullptr;
    static cudaEvent_t evFork = nullptr, evJoin = nullptr;
    if (!s2) {
        cudaStreamCreateWithFlags(&s2, cudaStreamNonBlocking);
        cudaEventCreateWithFlags(&evFork, cudaEventDisableTiming);
        cudaEventCreateWithFlags(&evJoin, cudaEventDisableTiming);
        cudaFuncSetAttribute(gemm_mma_kernel,
                             cudaFuncAttributeMaxDynamicSharedMemorySize, SM_TOTAL);
    }

    zero_cnt_kernel<<<208, 256>>>(W1);

    cudaEventRecord(evFork, 0);
    cudaStreamWaitEvent(s2, evFork, 0);

    int perAdj = (E + 7) / 8;
    int pblocks = (2 * perAdj + 255) / 256;
    place_kernel<<<pblocks, 256, 0, s2>>>(adj_row,  adj_col,  adj_val,
                                          adj2_row, adj2_col, adj2_val, E, perAdj);

    gemm_mma_kernel<<<(N_TOT + 127) / 128, GT, SM_TOTAL>>>(emb_node, emb_attri, x1);

    cudaEventRecord(evJoin, s2);
    cudaStreamWaitEvent(0, evJoin, 0);

    spmm_kernel<<<6375, 256>>>(x2, x3);

    spill_kernel<<<8, 256>>>(x1, x2, x3);
}

// round 17
// speedup vs baseline: 1.1867x; 1.0443x over previous
#include <cuda_runtime.h>
#include <cuda_fp16.h>
#include <cstdint>

#define N_NODE 100000
#define N_TOT  102000
#define NFEAT  256
#define NDIM   128
#define CAP    64
#define SPILL_MAX 8192

typedef unsigned long long u64;

// ===========================================================================
// Device scratch
// ===========================================================================
__device__ int  g_cnt[2][N_TOT];
__device__ u64  g_rec[2][(size_t)N_TOT * CAP];   // low32: col*NDIM, high32: val
__device__ int  g_spill_cnt;
__device__ int4 g_spill[SPILL_MAX];
__device__ __align__(16) uint4 g_Whi_pk[4096];   // 64 KB prepacked W (fp16)
__device__ __align__(16) __half g_x1h[(size_t)N_TOT * NDIM];  // 26 MB fp16 x1

// ---------------------------------------------------------------------------
__device__ __forceinline__ void pack16h(const float4* v, uint32_t* hp) {
    const float* f = (const float*)v;
#pragma unroll
    for (int i = 0; i < 8; i++) {
        __half h0 = __float2half_rn(f[2*i]);
        __half h1 = __float2half_rn(f[2*i+1]);
        hp[i] = (uint32_t)__half_as_ushort(h0) | ((uint32_t)__half_as_ushort(h1) << 16);
    }
}
__device__ __forceinline__ void pack8h(const float4* v, uint32_t* hp) {
    const float* f = (const float*)v;
#pragma unroll
    for (int i = 0; i < 4; i++) {
        __half h0 = __float2half_rn(f[2*i]);
        __half h1 = __float2half_rn(f[2*i+1]);
        hp[i] = (uint32_t)__half_as_ushort(h0) | ((uint32_t)__half_as_ushort(h1) << 16);
    }
}

// ---------------------------------------------------------------------------
// zero counters + (block 0) prepack W (fp16, swizzled tile layout)
// ---------------------------------------------------------------------------
__global__ void zero_cnt_kernel(const float* __restrict__ W) {
    int i = blockIdx.x * blockDim.x + threadIdx.x;
    int n = 2 * N_TOT;
    int stride = gridDim.x * blockDim.x;
    for (int j = i; j < n; j += stride)
        ((int*)g_cnt)[j] = 0;
    if (i == 0) g_spill_cnt = 0;

    if (blockIdx.x == 0) {
        const int t = threadIdx.x;
        const int r = t >> 1;
        const int half = t & 1;
        const float* wrow = W + (size_t)r * NFEAT;
        char* hB = (char*)g_Whi_pk;
        for (int ki = 0; ki < 8; ki++) {
            float4 v[4];
#pragma unroll
            for (int q = 0; q < 4; q++)
                v[q] = __ldg((const float4*)(wrow + ki * 32 + half * 16) + q);
            uint32_t hp[8];
            pack16h(v, hp);
            int sw = r & 3;
#pragma unroll
            for (int cc = 0; cc < 2; cc++) {
                int ch = (half * 2 + cc) ^ sw;
                int off = ki * 8192 + r * 64 + ch * 16;
                *(uint4*)(hB + off) = make_uint4(hp[cc*4], hp[cc*4+1], hp[cc*4+2], hp[cc*4+3]);
            }
        }
    }
}

// ---------------------------------------------------------------------------
// ELL placement (records carry col*NDIM)
// ---------------------------------------------------------------------------
__global__ __launch_bounds__(256) void place_kernel(
    const int* __restrict__ erow1, const int* __restrict__ ecol1, const float* __restrict__ eval1,
    const int* __restrict__ erow2, const int* __restrict__ ecol2, const float* __restrict__ eval2,
    int E, int perAdj)
{
    int idx = blockIdx.x * blockDim.x + threadIdx.x;
    int a = 0;
    if (idx >= perAdj) { a = 1; idx -= perAdj; if (idx >= perAdj) return; }
    const int*   erow = a ? erow2 : erow1;
    const int*   ecol = a ? ecol2 : ecol1;
    const float* eval = a ? eval2 : eval1;
    u64* rec = g_rec[a];
    int* cnt = g_cnt[a];

    int e0 = idx * 8;
    int nn = (e0 + 8 <= E) ? 8 : (E - e0);
    if (nn <= 0) return;

    int rr[8], cc[8]; float vv[8];
#pragma unroll
    for (int q = 0; q < 2; q++) {
        if (e0 + q * 4 + 4 <= E) {
            int4   r4 = *(const int4*)(erow + e0 + q * 4);
            int4   c4 = *(const int4*)(ecol + e0 + q * 4);
            float4 v4 = *(const float4*)(eval + e0 + q * 4);
            rr[q*4+0] = r4.x; rr[q*4+1] = r4.y; rr[q*4+2] = r4.z; rr[q*4+3] = r4.w;
            cc[q*4+0] = c4.x; cc[q*4+1] = c4.y; cc[q*4+2] = c4.z; cc[q*4+3] = c4.w;
            vv[q*4+0] = v4.x; vv[q*4+1] = v4.y; vv[q*4+2] = v4.z; vv[q*4+3] = v4.w;
        } else {
            for (int i = q * 4; i < nn; i++) {
                rr[i] = __ldg(erow + e0 + i);
                cc[i] = __ldg(ecol + e0 + i);
                vv[i] = __ldg(eval + e0 + i);
            }
        }
    }

    int pos[8];
#pragma unroll
    for (int i = 0; i < 8; i++)
        if (i < nn) pos[i] = atomicAdd(&cnt[rr[i]], 1);

#pragma unroll
    for (int i = 0; i < 8; i++) {
        if (i < nn) {
            u64 r8 = (u64)(unsigned)(cc[i] * NDIM)
                   | ((u64)__float_as_uint(vv[i]) << 32);
            if (pos[i] < CAP) {
                rec[(size_t)rr[i] * CAP + pos[i]] = r8;
            } else {
                int s = atomicAdd(&g_spill_cnt, 1);
                if (s < SPILL_MAX)
                    g_spill[s] = make_int4(rr[i] | (a << 30), cc[i],
                                           (int)__float_as_uint(vv[i]), 0);
            }
        }
    }
}

// ---------------------------------------------------------------------------
// SpMM v6: fp16 gathers, MLP=8, ONE shfl per edge (v cached in regs).
// ---------------------------------------------------------------------------
__global__ __launch_bounds__(256, 5) void spmm_kernel(
    float* __restrict__ x2, float* __restrict__ x3)
{
    const int lane  = threadIdx.x & 31;
    const int warp0 = (int)(((size_t)blockIdx.x * blockDim.x + threadIdx.x) >> 5);
    const int nw    = (gridDim.x * blockDim.x) >> 5;
    const __half* xh = g_x1h;

    for (int gw = warp0; gw < 2 * N_TOT; gw += nw) {
        const int a = (gw >= N_TOT) ? 1 : 0;
        const int r = a ? (gw - N_TOT) : gw;

        int m = g_cnt[a][r];
        if (m > CAP) m = CAP;
        const u64* rp = g_rec[a] + (size_t)r * CAP;

        u64 myrec = 0;
        if (lane < m) myrec = __ldg(rp + lane);

        float4 accA = make_float4(0.f, 0.f, 0.f, 0.f);
        float4 accB = make_float4(0.f, 0.f, 0.f, 0.f);
        const int m1 = (m < 32) ? m : 32;
        int k = 0;

        for (; k + 8 <= m1; k += 8) {
            uint2 u[8]; float v[8];
#pragma unroll
            for (int i = 0; i < 8; i++) {
                u64 q = __shfl_sync(0xffffffffu, myrec, k + i);
                v[i] = __uint_as_float((unsigned)(q >> 32));
                u[i] = __ldg((const uint2*)(xh + (unsigned)q) + lane);
            }
#pragma unroll
            for (int i = 0; i < 8; i++) {
                float2 f01 = __half22float2(*(const __half2*)&u[i].x);
                float2 f23 = __half22float2(*(const __half2*)&u[i].y);
                float4* A = (i & 1) ? &accB : &accA;
                A->x = fmaf(v[i], f01.x, A->x);
                A->y = fmaf(v[i], f01.y, A->y);
                A->z = fmaf(v[i], f23.x, A->z);
                A->w = fmaf(v[i], f23.y, A->w);
            }
        }
        for (; k < m1; k++) {
            u64 q = __shfl_sync(0xffffffffu, myrec, k);
            float v = __uint_as_float((unsigned)(q >> 32));
            uint2 u = __ldg((const uint2*)(xh + (unsigned)q) + lane);
            float2 f01 = __half22float2(*(const __half2*)&u.x);
            float2 f23 = __half22float2(*(const __half2*)&u.y);
            accA.x = fmaf(v, f01.x, accA.x);
            accA.y = fmaf(v, f01.y, accA.y);
            accA.z = fmaf(v, f23.x, accA.z);
            accA.w = fmaf(v, f23.y, accA.w);
        }
        for (; k < m; k++) {
            u64 q = __ldg(rp + k);
            float v = __uint_as_float((unsigned)(q >> 32));
            uint2 u = __ldg((const uint2*)(xh + (unsigned)q) + lane);
            float2 f01 = __half22float2(*(const __half2*)&u.x);
            float2 f23 = __half22float2(*(const __half2*)&u.y);
            accA.x = fmaf(v, f01.x, accA.x);
            accA.y = fmaf(v, f01.y, accA.y);
            accA.z = fmaf(v, f23.x, accA.z);
            accA.w = fmaf(v, f23.y, accA.w);
        }

        float4 acc;
        acc.x = accA.x + accB.x; acc.y = accA.y + accB.y;
        acc.z = accA.z + accB.z; acc.w = accA.w + accB.w;
        float* outp = (a ? x3 : x2) + (size_t)r * NDIM;
        ((float4*)outp)[lane] = acc;
    }
}

__global__ __launch_bounds__(256) void spill_kernel(
    const float* __restrict__ x1, float* __restrict__ x2, float* __restrict__ x3)
{
    int nspill = g_spill_cnt;
    if (nspill > SPILL_MAX) nspill = SPILL_MAX;
    int lane = threadIdx.x & 31;
    int warp = (blockIdx.x * blockDim.x + threadIdx.x) >> 5;
    int nwarps = (gridDim.x * blockDim.x) >> 5;
    for (int s = warp; s < nspill; s += nwarps) {
        int4 e = g_spill[s];
        int a = (e.x >> 30) & 1;
        int r = e.x & 0x3fffffff;
        float v = __uint_as_float((unsigned)e.z);
        float4 p = __ldg((const float4*)(x1 + (size_t)e.y * NDIM) + lane);
        float* dst = (a ? x3 : x2) + (size_t)r * NDIM + lane * 4;
        asm volatile("red.global.add.v4.f32 [%0], {%1, %2, %3, %4};"
                     :: "l"(dst), "f"(p.x * v), "f"(p.y * v), "f"(p.z * v), "f"(p.w * v)
                     : "memory");
    }
}

// ===========================================================================
// pure-fp16 warp-MMA GEMM v6: 1 MMA pass, W resident (64 KB), A double-buffered.
// ===========================================================================
__device__ __forceinline__ uint32_t smem_u32(const void* p) {
    uint32_t a;
    asm("{ .reg .u64 t; cvta.to.shared.u64 t, %1; cvt.u32.u64 %0, t; }"
        : "=r"(a) : "l"(p));
    return a;
}
__device__ __forceinline__ void ldmatrix4(uint32_t* r, uint32_t addr) {
    asm volatile("ldmatrix.sync.aligned.m8n8.x4.shared.b16 {%0,%1,%2,%3}, [%4];"
                 : "=r"(r[0]), "=r"(r[1]), "=r"(r[2]), "=r"(r[3]) : "r"(addr));
}
__device__ __forceinline__ void mma_f16(float* d, const uint32_t* a,
                                        uint32_t b0, uint32_t b1) {
    asm volatile("mma.sync.aligned.m16n8k16.row.col.f32.f16.f16.f32 "
                 "{%0,%1,%2,%3},{%4,%5,%6,%7},{%8,%9},{%0,%1,%2,%3};"
                 : "+f"(d[0]), "+f"(d[1]), "+f"(d[2]), "+f"(d[3])
                 : "r"(a[0]), "r"(a[1]), "r"(a[2]), "r"(a[3]), "r"(b0), "r"(b1));
}

#define GT       512
#define SM_WHI   0
#define SM_A     65536
#define SM_TOTAL 81920

__global__ __launch_bounds__(GT) void gemm_mma_kernel(
    const float* __restrict__ A0, const float* __restrict__ A1,
    float* __restrict__ C)
{
    extern __shared__ __align__(128) char smem[];
    const uint32_t sb = smem_u32(smem);

    const int t    = threadIdx.x;
    const int lane = t & 31;
    const int wid  = t >> 5;
    const int warpM = (wid & 3) * 32;
    const int warpN = (wid >> 2) * 32;
    const int blockRow = blockIdx.x * 128;

    {
        uint4* dh = (uint4*)(smem + SM_WHI);
#pragma unroll
        for (int i = 0; i < 8; i++)
            dh[t + i * GT] = g_Whi_pk[t + i * GT];
    }

    const int lrow = t >> 2;
    const int lq   = t & 3;
    const int grow = blockRow + lrow;
    const float* asrc = nullptr;
    if (grow < N_NODE)      asrc = A0 + (size_t)grow * NFEAT;
    else if (grow < N_TOT)  asrc = A1 + (size_t)(grow - N_NODE) * NFEAT;

    const int l15 = lane & 15;
    const int lk  = lane >> 4;

    float acc[2][4][4];
#pragma unroll
    for (int mt = 0; mt < 2; mt++)
#pragma unroll
        for (int nt = 0; nt < 4; nt++)
#pragma unroll
            for (int i = 0; i < 4; i++) acc[mt][nt][i] = 0.f;

    float4 pa[2];
#pragma unroll
    for (int i = 0; i < 2; i++)
        pa[i] = asrc ? __ldg((const float4*)(asrc + lq * 8) + i)
                     : make_float4(0.f, 0.f, 0.f, 0.f);
    {
        uint32_t hp[4];
        pack8h(pa, hp);
        char* hB = smem + SM_A;
        int ch = lq ^ (lrow & 3);
        *(uint4*)(hB + lrow * 64 + ch * 16) = make_uint4(hp[0], hp[1], hp[2], hp[3]);
    }
    __syncthreads();

    for (int ki = 0; ki < 8; ki++) {
        if (ki < 7) {
            const int kk = (ki + 1) * 32;
#pragma unroll
            for (int i = 0; i < 2; i++)
                pa[i] = asrc ? __ldg((const float4*)(asrc + kk + lq * 8) + i)
                             : make_float4(0.f, 0.f, 0.f, 0.f);
        }

        const uint32_t aHi = sb + SM_A + (uint32_t)(ki & 1) * 8192;
        const uint32_t wHi = sb + SM_WHI + (uint32_t)ki * 8192;

#pragma unroll
        for (int ks = 0; ks < 2; ks++) {
            uint32_t ah[2][4];
#pragma unroll
            for (int mt = 0; mt < 2; mt++) {
                int r  = warpM + mt * 16 + l15;
                int ch = ks * 2 + lk;
                uint32_t off = (uint32_t)(r * 64) + (uint32_t)((ch ^ (r & 3)) << 4);
                ldmatrix4(ah[mt], aHi + off);
            }
#pragma unroll
            for (int np = 0; np < 2; np++) {
                int rn = warpN + np * 16 + l15;
                int ch = ks * 2 + lk;
                uint32_t off = (uint32_t)(rn * 64) + (uint32_t)((ch ^ (rn & 3)) << 4);
                uint32_t bh[4];
                ldmatrix4(bh, wHi + off);
#pragma unroll
                for (int sub = 0; sub < 2; sub++) {
                    uint32_t bh0 = bh[sub], bh1 = bh[sub + 2];
                    int nt = np * 2 + sub;
#pragma unroll
                    for (int mt = 0; mt < 2; mt++)
                        mma_f16(acc[mt][nt], ah[mt], bh0, bh1);
                }
            }
        }

        if (ki < 7) {
            uint32_t hp[4];
            pack8h(pa, hp);
            char* hB = smem + SM_A + ((ki + 1) & 1) * 8192;
            int ch = lq ^ (lrow & 3);
            *(uint4*)(hB + lrow * 64 + ch * 16) = make_uint4(hp[0], hp[1], hp[2], hp[3]);
        }
        __syncthreads();
    }

    const int erow = blockRow + warpM + (lane >> 2);
    const int ecol0 = (lane & 3) * 2;
#pragma unroll
    for (int mt = 0; mt < 2; mt++) {
        int r0 = erow + mt * 16;
#pragma unroll
        for (int nt = 0; nt < 4; nt++) {
            const float* d = acc[mt][nt];
            int col = warpN + nt * 8 + ecol0;
            if (r0 < N_TOT) {
                *(float2*)(C + (size_t)r0 * NDIM + col) = make_float2(d[0], d[1]);
                *(__half2*)(g_x1h + (size_t)r0 * NDIM + col) =
                    __floats2half2_rn(d[0], d[1]);
            }
            if (r0 + 8 < N_TOT) {
                *(float2*)(C + (size_t)(r0 + 8) * NDIM + col) = make_float2(d[2], d[3]);
                *(__half2*)(g_x1h + (size_t)(r0 + 8) * NDIM + col) =
                    __floats2half2_rn(d[2], d[3]);
            }
        }
    }
}

// ===========================================================================
extern "C" void kernel_launch(void* const* d_in, const int* in_sizes, int n_in,
                              void* d_out, int out_size)
{
    const float* emb_node  = (const float*)d_in[0];
    const float* emb_attri = (const float*)d_in[1];
    const float* W1        = (const float*)d_in[2];
    const int*   adj_row   = (const int*)d_in[3];
    const int*   adj_col   = (const int*)d_in[4];
    const float* adj_val   = (const float*)d_in[5];
    const int*   adj2_row  = (const int*)d_in[6];
    const int*   adj2_col  = (const int*)d_in[7];
    const float* adj2_val  = (const float*)d_in[8];

    float* out = (float*)d_out;
    float* x1 = out;
    float* x2 = out + (size_t)N_TOT * NDIM;
    float* x3 = x2  + (size_t)N_TOT * NDIM;

    const int E = in_sizes[3];

    static cudaStream_t s2 = nullptr;
    static cudaEvent_t evFork = nullptr, evJoin = nullptr;
    if (!s2) {
        cudaStreamCreateWithFlags(&s2, cudaStreamNonBlocking);
        cudaEventCreateWithFlags(&evFork, cudaEventDisableTiming);
        cudaEventCreateWithFlags(&evJoin, cudaEventDisableTiming);
        cudaFuncSetAttribute(gemm_mma_kernel,
                             cudaFuncAttributeMaxDynamicSharedMemorySize, SM_TOTAL);
    }

    zero_cnt_kernel<<<208, 256>>>(W1);

    cudaEventRecord(evFork, 0);
    cudaStreamWaitEvent(s2, evFork, 0);

    int perAdj = (E + 7) / 8;
    int pblocks = (2 * perAdj + 255) / 256;
    place_kernel<<<pblocks, 256, 0, s2>>>(adj_row,  adj_col,  adj_val,
                                          adj2_row, adj2_col, adj2_val, E, perAdj);

    gemm_mma_kernel<<<(N_TOT + 127) / 128, GT, SM_TOTAL>>>(emb_node, emb_attri, x1);

    cudaEventRecord(evJoin, s2);
    cudaStreamWaitEvent(0, evJoin, 0);

    spmm_kernel<<<6375, 256>>>(x2, x3);

    spill_kernel<<<8, 256>>>(x1, x2, x3);
}